// round 6
// baseline (speedup 1.0000x reference)
#include <cuda_runtime.h>

#define MAX_N 100000
#define D_FEAT 64
#define N_ETYPES 8
#define EPS_V 1e-8f

// Scratch — static __device__ globals (no runtime allocation). Counters are 0
// at module load; the elected last block restores them before exiting, so
// every graph replay starts from identical state.
__device__ float         g_nw_exp[MAX_N];
__device__ float         g_sum[MAX_N];
__device__ unsigned char g_mask[MAX_N];
__device__ float         g_ft[MAX_N * D_FEAT];
__device__ float         g_ew[N_ETYPES];
__device__ int           g_zero_count;   // # of all-zero feature rows
__device__ int           g_done;         // block arrival counter

// Scoped acquire-release atomic: native ATOMG.STRONG.GPU on sm_103a.
// Release: orders this block's prior stores (mask/nw_exp/ew) to gpu scope.
// Acquire: the elected block observes every earlier block's released writes.
// Crucially: NO CCTL.IVALL (unlike __threadfence()), so it is cheap.
__device__ __forceinline__ int atom_add_acq_rel(int* a, int v)
{
    int old;
    asm volatile("atom.acq_rel.gpu.global.add.s32 %0, [%1], %2;"
                 : "=r"(old) : "l"(a), "r"(v) : "memory");
    return old;
}

// ---------------------------------------------------------------------------
// Single fused kernel.
//  Phase 1 (all blocks): node pass — 8 lanes per node, 2×float4 per lane.
//    Nonzero nodes (always, in practice): out = feat, written streaming.
//  Arrival: one acq_rel atomic per block; last block is elected.
//  Phase 2 (elected block, only if some all-zero row exists): full edge
//    scatter + finalize with this one block. Correctness-only path.
// ---------------------------------------------------------------------------
__global__ void __launch_bounds__(512) k_fused(
    const float4* __restrict__ feat4,             // [N*16]
    const float4* __restrict__ attn4,             // [16]
    const float*  __restrict__ edge_weight,       // [T,T]
    const float*  __restrict__ edge_weight_param, // [T,1]
    const int*    __restrict__ src,
    const int*    __restrict__ dst,
    const int*    __restrict__ e_feat,
    float4*       __restrict__ out4,              // [N*16]
    int N, int E)
{
    // ---------------- Phase 1: node pass ----------------
    const int tid = blockIdx.x * blockDim.x + threadIdx.x;
    const int n   = tid >> 3;            // 8 threads per node
    const int sub = threadIdx.x & 7;

    if (n < N) {
        const size_t base = (size_t)n * 16 + sub * 2;
        const float4 f0 = __ldcs(feat4 + base);        // evict-first streaming
        const float4 f1 = __ldcs(feat4 + base + 1);
        const float4 a0 = __ldg(attn4 + sub * 2);
        const float4 a1 = __ldg(attn4 + sub * 2 + 1);

        float s_abs = fabsf(f0.x) + fabsf(f0.y) + fabsf(f0.z) + fabsf(f0.w)
                    + fabsf(f1.x) + fabsf(f1.y) + fabsf(f1.z) + fabsf(f1.w);
        float s_dot = f0.x*a0.x + f0.y*a0.y + f0.z*a0.z + f0.w*a0.w
                    + f1.x*a1.x + f1.y*a1.y + f1.z*a1.z + f1.w*a1.w;

        // 8-lane group reduce; mask restricted to the group (the tail block
        // may have whole inactive groups — never partial ones).
        const unsigned gmask = 0xFFu << (threadIdx.x & 24);
        #pragma unroll
        for (int off = 4; off > 0; off >>= 1) {
            s_abs += __shfl_xor_sync(gmask, s_abs, off);
            s_dot += __shfl_xor_sync(gmask, s_dot, off);
        }

        const bool zero_node = (s_abs == 0.0f);

        if (sub == 0) {
            g_mask[n]   = zero_node ? 0 : 1;
            g_nw_exp[n] = zero_node ? 0.0f : expf(s_dot);  // TEMPERATURE==1
            if (zero_node) atomicAdd(&g_zero_count, 1);
        }

        if (!zero_node) {
            __stcs(out4 + base,     f0);                   // out == feat
            __stcs(out4 + base + 1, f1);
        } else {
            const float4 z = make_float4(0.f, 0.f, 0.f, 0.f);
            reinterpret_cast<float4*>(g_ft)[base]     = z;
            reinterpret_cast<float4*>(g_ft)[base + 1] = z;
        }
    }

    // Block 0 builds the per-edge-type weight table (rare-path consumer is
    // ordered behind the release/acquire arrival chain).
    if (blockIdx.x == 0 && threadIdx.x < N_ETYPES) {
        float acc = 0.f;
        #pragma unroll
        for (int j = 0; j < N_ETYPES; ++j)
            acc += edge_weight[threadIdx.x * N_ETYPES + j] * edge_weight_param[j];
        g_ew[threadIdx.x] = acc + 1.0f;
    }

    // ---------------- Arrival / election ----------------
    __shared__ int s_zc;
    __syncthreads();
    if (threadIdx.x == 0) {
        int zc = -1;   // -1 => not elected
        if (atom_add_acq_rel(&g_done, 1) == (int)gridDim.x - 1) {
            zc = g_zero_count;   // coherent: counter only ever touched by atomics
            g_done = 0;          // restore invariant for next graph replay
        }
        s_zc = zc;
    }
    __syncthreads();
    const int zc = s_zc;
    if (zc <= 0) return;   // not elected, or elected with no zero rows (common)

    // ---------------- Phase 2: rare path, elected block only ----------------
    __threadfence();   // one L1 invalidate so we observe peers' plain stores

    const int t  = threadIdx.x;
    const int BT = blockDim.x;

    // zero the normalizer accumulators
    for (int i = t; i < N; i += BT) g_sum[i] = 0.0f;
    __syncthreads();

    // edge scatter (only destinations with zero-mask matter)
    const float* feat = (const float*)feat4;
    for (int e = t; e < E; e += BT) {
        const int d = dst[e];
        if (g_mask[d] != 0) continue;
        const int s = src[e];
        const float w = g_nw_exp[s];
        atomicAdd(&g_sum[d], w);
        if (w != 0.0f) {
            const float sc = w * g_ew[e_feat[e] - 1];
            const float* fs = feat + (size_t)s * D_FEAT;
            float* fd = g_ft + (size_t)d * D_FEAT;
            #pragma unroll
            for (int k = 0; k < D_FEAT; ++k)
                atomicAdd(fd + k, fs[k] * sc);
        }
    }
    __syncthreads();

    // finalize zero-mask nodes: out = ft / denom
    for (int idx = t; idx < N * 16; idx += BT) {
        const int nn = idx >> 4;
        if (g_mask[nn] != 0) continue;
        const int ss = idx & 15;
        const float sm = g_sum[nn];
        const float inv = 1.0f / ((sm < EPS_V) ? 1.0f : sm);
        const float4 v = reinterpret_cast<const float4*>(g_ft)[(size_t)nn * 16 + ss];
        out4[(size_t)nn * 16 + ss] =
            make_float4(v.x * inv, v.y * inv, v.z * inv, v.w * inv);
    }
    __syncthreads();
    if (t == 0) g_zero_count = 0;   // restore invariant
}

// ---------------------------------------------------------------------------
extern "C" void kernel_launch(void* const* d_in, const int* in_sizes, int n_in,
                              void* d_out, int out_size)
{
    const float* feat              = (const float*)d_in[0];
    const float* attn              = (const float*)d_in[1];
    const float* edge_weight       = (const float*)d_in[2];
    const float* edge_weight_param = (const float*)d_in[3];
    const int*   src               = (const int*)d_in[4];
    const int*   dst               = (const int*)d_in[5];
    const int*   e_feat            = (const int*)d_in[6];
    float*       out               = (float*)d_out;

    const int N = in_sizes[0] / D_FEAT;   // 100000
    const int E = in_sizes[4];            // 1000000

    const int threads = 512;              // 64 nodes per block (8 lanes/node)
    const int grid = (N * 8 + threads - 1) / threads;   // 1563

    k_fused<<<grid, threads>>>((const float4*)feat, (const float4*)attn,
                               edge_weight, edge_weight_param,
                               src, dst, e_feat,
                               (float4*)out, N, E);
}

// round 7
// speedup vs baseline: 1.3499x; 1.3499x over previous
#include <cuda_runtime.h>

#define D_FEAT 64
#define N_ETYPES 8
#define EPS_V 1e-8f

// ---------------------------------------------------------------------------
// Single kernel, zero cross-block coordination.
//
// Layout: 16 lanes per node (one float4 per lane), 2 nodes per warp.
//
// Common path (node row nonzero — always, in practice):
//   load float4 -> nonzero test -> warp ballot -> store float4. Nothing else.
//
// Rare path (some node row is exactly all-zero): the OWNING WARP alone
// computes that node's full aggregation by scanning all E edges and
// recomputing per-source attention weights directly from feat. Slow but
// correct, fully self-contained — requires no data from other blocks.
// ---------------------------------------------------------------------------
__global__ void __launch_bounds__(256, 4) k_aplayer(
    const float4* __restrict__ feat4,             // [N*16]
    const float4* __restrict__ attn4,             // [16]
    const float*  __restrict__ edge_weight,       // [T,T]
    const float*  __restrict__ edge_weight_param, // [T,1]
    const int*    __restrict__ src,
    const int*    __restrict__ dst,
    const int*    __restrict__ e_feat,
    float4*       __restrict__ out4,              // [N*16]
    int N, int E)
{
    const int tid  = blockIdx.x * blockDim.x + threadIdx.x;
    const int lane = threadIdx.x & 31;
    const int half = lane >> 4;            // which of the warp's 2 nodes
    const int sub  = lane & 15;            // float4 slot within the node row
    const int n    = tid >> 4;             // this thread's node

    float4 f = make_float4(0.f, 0.f, 0.f, 0.f);
    bool in_range = (n < N);
    if (in_range) f = __ldcs(feat4 + (size_t)n * 16 + sub);

    // Per-chunk nonzero test. (NaN != 0 -> nonzero; -0.0 == 0 -> zero;
    // identical semantics to sum(|f|) == 0 in the reference.)
    const bool chunk_nz = (f.x != 0.f) | (f.y != 0.f) | (f.z != 0.f) | (f.w != 0.f);
    const unsigned bal = __ballot_sync(0xFFFFFFFFu, chunk_nz);

    const bool my_node_zero = in_range &&
        (((bal >> (half * 16)) & 0xFFFFu) == 0u);

    if (!my_node_zero && in_range) {
        __stcs(out4 + (size_t)n * 16 + sub, f);   // out == feat, bit-exact
    }

    // Warp-uniform: does this warp own any all-zero node?
    if (__ballot_sync(0xFFFFFFFFu, my_node_zero) == 0u)
        return;                                    // common path ends here

    // ======================= RARE PATH (warp-local) =======================
    // Build the per-edge-type weight table: lane t (t<8) holds ew[t].
    float my_ew = 0.f;
    if (lane < N_ETYPES) {
        float acc = 0.f;
        #pragma unroll
        for (int j = 0; j < N_ETYPES; ++j)
            acc += edge_weight[lane * N_ETYPES + j] * edge_weight_param[j];
        my_ew = acc + 1.0f;
    }

    // Attention vector chunk for lanes 0..15 (used to recompute nw_exp(src)).
    const float4 a = __ldg(attn4 + sub);

    // Process each zero node owned by this warp (at most 2), full warp each.
    const int node_base = (blockIdx.x * blockDim.x + (threadIdx.x & ~31)) >> 4;
    #pragma unroll
    for (int h = 0; h < 2; ++h) {
        const int zn = node_base + h;
        const bool zn_zero = (((bal >> (h * 16)) & 0xFFFFu) == 0u) && (zn < N);
        if (!zn_zero) continue;

        float4 acc   = make_float4(0.f, 0.f, 0.f, 0.f);  // lanes 0..15: chunk sub
        float  denom = 0.f;                               // replicated in all lanes

        for (int e = lane; e < E; e += 32) {
            const bool match = (dst[e] == zn);
            unsigned m = __ballot_sync(0xFFFFFFFFu, match);
            while (m) {
                const int src_lane = __ffs(m) - 1;
                m &= m - 1;
                const int ee = (e - lane) + src_lane;      // matching edge id
                const int s  = src[ee];
                const int et = e_feat[ee];

                // Recompute w = exp(feat[s]·attn) * (feat[s] nonzero ? 1 : 0)
                float4 fs = make_float4(0.f, 0.f, 0.f, 0.f);
                if (lane < 16) fs = feat4[(size_t)s * 16 + sub];
                float s_abs = fabsf(fs.x) + fabsf(fs.y) + fabsf(fs.z) + fabsf(fs.w);
                float s_dot = fs.x * a.x + fs.y * a.y + fs.z * a.z + fs.w * a.w;
                #pragma unroll
                for (int off = 16; off > 0; off >>= 1) {   // lanes 16..31 add 0
                    s_abs += __shfl_xor_sync(0xFFFFFFFFu, s_abs, off);
                    s_dot += __shfl_xor_sync(0xFFFFFFFFu, s_dot, off);
                }
                const float w = (s_abs == 0.f) ? 0.f : expf(s_dot); // T == 1
                denom += w;
                const float ew = __shfl_sync(0xFFFFFFFFu, my_ew, et - 1);
                const float sc = w * ew;
                if (lane < 16) {
                    acc.x += fs.x * sc; acc.y += fs.y * sc;
                    acc.z += fs.z * sc; acc.w += fs.w * sc;
                }
            }
        }

        const float dn  = (denom < EPS_V) ? 1.0f : denom;
        const float inv = 1.0f / dn;
        if (lane < 16) {
            out4[(size_t)zn * 16 + lane] =
                make_float4(acc.x * inv, acc.y * inv, acc.z * inv, acc.w * inv);
        }
    }
}

// ---------------------------------------------------------------------------
extern "C" void kernel_launch(void* const* d_in, const int* in_sizes, int n_in,
                              void* d_out, int out_size)
{
    const float* feat              = (const float*)d_in[0];
    const float* attn              = (const float*)d_in[1];
    const float* edge_weight       = (const float*)d_in[2];
    const float* edge_weight_param = (const float*)d_in[3];
    const int*   src               = (const int*)d_in[4];
    const int*   dst               = (const int*)d_in[5];
    const int*   e_feat            = (const int*)d_in[6];
    float*       out               = (float*)d_out;

    const int N = in_sizes[0] / D_FEAT;   // 100000
    const int E = in_sizes[4];            // 1000000

    const int threads = 256;              // 16 nodes per block
    const int grid = (N * 16 + threads - 1) / threads;   // 6250

    k_aplayer<<<grid, threads>>>((const float4*)feat, (const float4*)attn,
                                 edge_weight, edge_weight_param,
                                 src, dst, e_feat,
                                 (float4*)out, N, E);
}